// round 2
// baseline (speedup 1.0000x reference)
#include <cuda_runtime.h>
#include <math.h>
#include <stdint.h>

// SSIM loss, separable 11-tap Gaussian, packed f32x2 arithmetic (sm_103a FFMA2).
// Pass 1: vertical conv, packed over x (aligned LDS.64 pairs).
// Pass 2: horizontal conv, packed over y (intermediate stored as float2[y-pair][x]).
// Only 4 convolutions needed: m1=conv(p), m2=conv(t), S=conv(p^2+t^2), X=conv(p*t).

#define KW      11
#define HALO    5
#define TILE_X  64
#define TILE_Y  32
#define IN_W    74              // TILE_X + 2*HALO
#define IN_H    42              // TILE_Y + 2*HALO
#define IN_WP   76              // padded row length (floats), even for LDS.64
#define VT_W    75              // VT row length in float2 (x extent 74, pad 1)
#define VT_ARR  (16 * VT_W)     // float2 per intermediate array
#define NYP     16              // y-pairs per tile
#define NXP     37              // x-pairs in halo width (74/2)
#define IMG     512
#define NCHAN   48
#define NT      256

#define C1F 1.0e-4f
#define C2F 9.0e-4f

// dynamic smem layout (float units)
#define SP_OFF  0
#define ST_OFF  (IN_H * IN_WP)                 // 3192
#define VT_OFF  (2 * IN_H * IN_WP)             // 6384 (float2 region starts here)
#define SMEM_BYTES ((2 * IN_H * IN_WP + 4 * VT_ARR * 2) * 4)   // 63936

__device__ double g_accum;   // zero-initialized at module load; finalize self-resets

// ---------------- packed f32x2 helpers ----------------
__device__ __forceinline__ uint64_t pk2(float x, float y) {
    uint64_t r; asm("mov.b64 %0, {%1, %2};" : "=l"(r) : "f"(x), "f"(y)); return r;
}
__device__ __forceinline__ float2 up2(uint64_t v) {
    float2 r; asm("mov.b64 {%0, %1}, %2;" : "=f"(r.x), "=f"(r.y) : "l"(v)); return r;
}
__device__ __forceinline__ uint64_t fma2(uint64_t a, uint64_t b, uint64_t c) {
    uint64_t d; asm("fma.rn.f32x2 %0, %1, %2, %3;" : "=l"(d) : "l"(a), "l"(b), "l"(c)); return d;
}
__device__ __forceinline__ uint64_t mul2(uint64_t a, uint64_t b) {
    uint64_t d; asm("mul.rn.f32x2 %0, %1, %2;" : "=l"(d) : "l"(a), "l"(b)); return d;
}
__device__ __forceinline__ uint64_t add2(uint64_t a, uint64_t b) {
    uint64_t d; asm("add.rn.f32x2 %0, %1, %2;" : "=l"(d) : "l"(a), "l"(b)); return d;
}

__global__ void __launch_bounds__(NT, 2) ssim_kernel(
    const float* __restrict__ pred,
    const float* __restrict__ target,
    const float* __restrict__ window)
{
    extern __shared__ float smem[];
    __shared__ float sg[KW];
    __shared__ float warp_sums[NT / 32];

    float* sp = smem + SP_OFF;
    float* st = smem + ST_OFF;
    float2* vt = reinterpret_cast<float2*>(smem + VT_OFF);

    const int tid = threadIdx.x;

    // 1D taps from 2D outer-product window diagonal: g[i] = sqrt(w[i][i])
    if (tid < KW) sg[tid] = sqrtf(window[tid * KW + tid]);

    // ---- load 42x74 halo tile (zero padded) ----
    const int gx0 = blockIdx.x * TILE_X - HALO;
    const int gy0 = blockIdx.y * TILE_Y - HALO;
    const size_t plane = (size_t)blockIdx.z * (IMG * IMG);
    const float* __restrict__ pb = pred + plane;
    const float* __restrict__ tb = target + plane;

    for (int i = tid; i < IN_H * IN_W; i += NT) {
        int y = i / IN_W, x = i - y * IN_W;
        int gx = gx0 + x, gy = gy0 + y;
        float p = 0.f, t = 0.f;
        if ((unsigned)gx < IMG && (unsigned)gy < IMG) {
            int off = gy * IMG + gx;
            p = pb[off];
            t = tb[off];
        }
        sp[y * IN_WP + x] = p;
        st[y * IN_WP + x] = t;
    }
    __syncthreads();

    // broadcast taps into packed registers
    uint64_t wk2[KW];
    #pragma unroll
    for (int k = 0; k < KW; k++) wk2[k] = pk2(sg[k], sg[k]);

    // ================= pass 1: vertical conv (packed over x) =================
    // item = (yg, xp): rows 2yg, 2yg+1 of the output, x-pair 2xp..2xp+1.
    // 4 arrays: m1 (p), m2 (t), S (p^2+t^2), X (p*t).
    for (int it = tid; it < NYP * NXP; it += NT) {
        int yg = it / NXP;
        int xp = it - yg * NXP;
        const float* pp = sp + (2 * yg) * IN_WP + 2 * xp;
        const float* tp = st + (2 * yg) * IN_WP + 2 * xp;

        uint64_t m1a = 0, m2a = 0, Sa = 0, Xa = 0;   // row 2yg
        uint64_t m1b = 0, m2b = 0, Sb = 0, Xb = 0;   // row 2yg+1

        #pragma unroll
        for (int k = 0; k < KW + 1; k++) {
            uint64_t p = *reinterpret_cast<const uint64_t*>(pp + k * IN_WP);
            uint64_t t = *reinterpret_cast<const uint64_t*>(tp + k * IN_WP);
            uint64_t x = mul2(p, t);
            uint64_t s = fma2(p, p, mul2(t, t));
            if (k < KW) {
                uint64_t w = wk2[k];
                m1a = fma2(w, p, m1a); m2a = fma2(w, t, m2a);
                Sa  = fma2(w, s, Sa);  Xa  = fma2(w, x, Xa);
            }
            if (k > 0) {
                uint64_t w = wk2[k - 1];
                m1b = fma2(w, p, m1b); m2b = fma2(w, t, m2b);
                Sb  = fma2(w, s, Sb);  Xb  = fma2(w, x, Xb);
            }
        }

        // store transposed-to-pairs: vt[a][yg][x].x = row 2yg, .y = row 2yg+1
        int o = yg * VT_W + 2 * xp;
        {
            float2 A = up2(m1a), B = up2(m1b);
            vt[0 * VT_ARR + o]     = make_float2(A.x, B.x);
            vt[0 * VT_ARR + o + 1] = make_float2(A.y, B.y);
        }
        {
            float2 A = up2(m2a), B = up2(m2b);
            vt[1 * VT_ARR + o]     = make_float2(A.x, B.x);
            vt[1 * VT_ARR + o + 1] = make_float2(A.y, B.y);
        }
        {
            float2 A = up2(Sa), B = up2(Sb);
            vt[2 * VT_ARR + o]     = make_float2(A.x, B.x);
            vt[2 * VT_ARR + o + 1] = make_float2(A.y, B.y);
        }
        {
            float2 A = up2(Xa), B = up2(Xb);
            vt[3 * VT_ARR + o]     = make_float2(A.x, B.x);
            vt[3 * VT_ARR + o + 1] = make_float2(A.y, B.y);
        }
    }
    __syncthreads();

    // ================= pass 2: horizontal conv (packed over y) =================
    // 256 items, one per thread: yp = tid&15 (fastest -> conflict-free LDS.64),
    // xg = tid>>4 covering 4 x outputs.
    const int yp = tid & 15;
    const int xg = tid >> 4;
    const int x0 = 4 * xg;

    uint64_t am1[4] = {0, 0, 0, 0};
    uint64_t am2[4] = {0, 0, 0, 0};
    uint64_t aS[4]  = {0, 0, 0, 0};
    uint64_t aX[4]  = {0, 0, 0, 0};

    const uint64_t* v0 = reinterpret_cast<const uint64_t*>(vt + 0 * VT_ARR + yp * VT_W + x0);
    const uint64_t* v1 = reinterpret_cast<const uint64_t*>(vt + 1 * VT_ARR + yp * VT_W + x0);
    const uint64_t* v2 = reinterpret_cast<const uint64_t*>(vt + 2 * VT_ARR + yp * VT_W + x0);
    const uint64_t* v3 = reinterpret_cast<const uint64_t*>(vt + 3 * VT_ARR + yp * VT_W + x0);

    #pragma unroll
    for (int k = 0; k < KW + 3; k++) {
        uint64_t a = v0[k], b = v1[k], c = v2[k], d = v3[k];
        #pragma unroll
        for (int o = 0; o < 4; o++) {
            int ki = k - o;
            if (ki >= 0 && ki < KW) {
                uint64_t w = wk2[ki];
                am1[o] = fma2(w, a, am1[o]);
                am2[o] = fma2(w, b, am2[o]);
                aS[o]  = fma2(w, c, aS[o]);
                aX[o]  = fma2(w, d, aX[o]);
            }
        }
    }

    // ---- SSIM map (packed pair over y) + accumulate ----
    const uint64_t TWO2  = pk2(2.f, 2.f);
    const uint64_t NEG12 = pk2(-1.f, -1.f);
    const uint64_t C1V   = pk2(C1F, C1F);
    const uint64_t C2V   = pk2(C2F, C2F);

    float lsum = 0.f;
    #pragma unroll
    for (int o = 0; o < 4; o++) {
        uint64_t mu1 = am1[o], mu2 = am2[o];
        uint64_t mu1s = mul2(mu1, mu1);
        uint64_t mu2s = mul2(mu2, mu2);
        uint64_t mu12 = mul2(mu1, mu2);
        uint64_t msum = add2(mu1s, mu2s);
        // num = (2*mu12 + C1) * (2*(X - mu12) + C2)
        uint64_t n1 = fma2(mu12, TWO2, C1V);
        uint64_t s12 = fma2(mu12, NEG12, aX[o]);          // X - mu12
        uint64_t n2 = fma2(s12, TWO2, C2V);
        uint64_t num = mul2(n1, n2);
        // den = (mu1s + mu2s + C1) * (S - msum + C2)
        uint64_t d1 = add2(msum, C1V);
        uint64_t d2 = add2(fma2(msum, NEG12, aS[o]), C2V); // S - msum + C2
        uint64_t den = mul2(d1, d2);
        float2 nf = up2(num), df = up2(den);
        lsum += __fdividef(nf.x, df.x);
        lsum += __fdividef(nf.y, df.y);
    }

    // ---- block reduce + global atomic ----
    #pragma unroll
    for (int off = 16; off > 0; off >>= 1)
        lsum += __shfl_down_sync(0xffffffffu, lsum, off);
    if ((tid & 31) == 0) warp_sums[tid >> 5] = lsum;
    __syncthreads();
    if (tid == 0) {
        float s = 0.f;
        #pragma unroll
        for (int i = 0; i < NT / 32; i++) s += warp_sums[i];
        atomicAdd(&g_accum, (double)s);
    }
}

__global__ void finalize_kernel(float* __restrict__ out) {
    const double n = (double)NCHAN * IMG * IMG;
    out[0] = (float)(1.0 - g_accum / n);
    g_accum = 0.0;   // self-reset so the graph replays deterministically
}

extern "C" void kernel_launch(void* const* d_in, const int* in_sizes, int n_in,
                              void* d_out, int out_size)
{
    const float* pred   = (const float*)d_in[0];
    const float* target = (const float*)d_in[1];
    const float* window = (const float*)d_in[2];
    float* out = (float*)d_out;

    static bool attr_set = false;
    if (!attr_set) {
        cudaFuncSetAttribute(ssim_kernel, cudaFuncAttributeMaxDynamicSharedMemorySize, SMEM_BYTES);
        attr_set = true;
    }

    dim3 grid(IMG / TILE_X, IMG / TILE_Y, NCHAN);
    ssim_kernel<<<grid, NT, SMEM_BYTES>>>(pred, target, window);
    finalize_kernel<<<1, 1>>>(out);
}